// round 1
// baseline (speedup 1.0000x reference)
#include <cuda_runtime.h>
#include <cuda_bf16.h>
#include <math.h>

#define TT   8192
#define HD   1024
#define G4H  4096
#define UNITS 14      // hidden units per block (both dirs: 2048 units over 148 blocks)
#define NROWS (UNITS*4)
#define NBLK 148
#define SMEM_WS (NROWS*HD*4)   // 229376 bytes

// ---------------- static device scratch (no allocs allowed) ----------------
__device__ float    g_xg[2][TT][G4H];        // per-direction input contributions (reused L0/L1)
__device__ float    g_h0[(size_t)TT*2048];   // layer0 output [T,2H]
__device__ float    g_h1[(size_t)TT*2048];   // layer1 output [T,2H]
__device__ float    g_feats[TT*5];
__device__ float    g_hbuf[2][2][HD];        // [dir][ping][H]
__device__ unsigned g_bar;

// ---------------- init: zero h state + barrier ----------------
__global__ void init_kernel() {
    int i = blockIdx.x * blockDim.x + threadIdx.x;
    if (i < 2*2*HD) ((float*)g_hbuf)[i] = 0.f;
    if (i == 0) g_bar = 0u;
}

// ---------------- fp32 SGEMM: C[m,n] = sum_k A[m,k]*W[n,k] + b1[n]+b2[n] ----------------
#define BM 128
#define BN 128
#define BK 16
__global__ void __launch_bounds__(256) sgemm_bias(
    const float* __restrict__ A, const float* __restrict__ W,
    const float* __restrict__ b1, const float* __restrict__ b2,
    float* __restrict__ C, int M, int N, int K)
{
    __shared__ float As[BK][BM+4];
    __shared__ float Bs[BK][BN+4];
    const int tid = threadIdx.x;
    const int bm0 = blockIdx.y * BM;
    const int bn0 = blockIdx.x * BN;
    const int tx = tid & 15, ty = tid >> 4;
    const int lrow = tid >> 2;          // 0..63
    const int lc4  = (tid & 3) * 4;     // 0,4,8,12

    float acc[8][8];
    #pragma unroll
    for (int i = 0; i < 8; i++)
        #pragma unroll
        for (int j = 0; j < 8; j++) acc[i][j] = 0.f;

    for (int k0 = 0; k0 < K; k0 += BK) {
        #pragma unroll
        for (int h = 0; h < 2; h++) {
            int row = lrow + h*64;
            float4 va = *(const float4*)(A + (size_t)(bm0+row)*K + k0 + lc4);
            As[lc4+0][row] = va.x; As[lc4+1][row] = va.y;
            As[lc4+2][row] = va.z; As[lc4+3][row] = va.w;
            float4 vb = *(const float4*)(W + (size_t)(bn0+row)*K + k0 + lc4);
            Bs[lc4+0][row] = vb.x; Bs[lc4+1][row] = vb.y;
            Bs[lc4+2][row] = vb.z; Bs[lc4+3][row] = vb.w;
        }
        __syncthreads();
        #pragma unroll
        for (int kk = 0; kk < BK; kk++) {
            float a[8], b[8];
            #pragma unroll
            for (int i = 0; i < 8; i++) a[i] = As[kk][ty*8+i];
            #pragma unroll
            for (int j = 0; j < 8; j++) b[j] = Bs[kk][tx*8+j];
            #pragma unroll
            for (int i = 0; i < 8; i++)
                #pragma unroll
                for (int j = 0; j < 8; j++) acc[i][j] = fmaf(a[i], b[j], acc[i][j]);
        }
        __syncthreads();
    }
    float bv[8];
    #pragma unroll
    for (int j = 0; j < 8; j++) { int n = bn0 + tx*8 + j; bv[j] = b1[n] + b2[n]; }
    #pragma unroll
    for (int i = 0; i < 8; i++) {
        size_t mrow = (size_t)(bm0 + ty*8 + i) * N;
        #pragma unroll
        for (int j = 0; j < 8; j++) C[mrow + bn0 + tx*8 + j] = acc[i][j] + bv[j];
    }
}

// ---------------- persistent bidirectional LSTM layer ----------------
// 148 blocks, 256 threads. Block b owns units [b*14, b*14+14) of 2048 (dir = u>>10).
// W_hh slice (56 rows x 1024 fp32 = 229KB) resident in dynamic smem for all 8192 steps.
// Global step barrier via monotone atomic counter; h broadcast through L2 (__ldcg/__stcg).
__global__ void __launch_bounds__(256, 1) lstm_kernel(
    const float* __restrict__ xgf, const float* __restrict__ xgb,
    const float* __restrict__ whf, const float* __restrict__ whb,
    float* __restrict__ hout)
{
    extern __shared__ float ws[];
    __shared__ float dot_s[NROWS];
    __shared__ float c_s[UNITS];
    const int tid = threadIdx.x;
    const int u0  = blockIdx.x * UNITS;

    // stage weight slice into smem (coalesced float4)
    for (int lr = 0; lr < NROWS; lr++) {
        int u = u0 + (lr >> 2);
        if (u >= 2*HD) break;
        int gate = lr & 3, dir = u >> 10, j = u & (HD-1);
        const float* src = (dir ? whb : whf) + ((size_t)((gate << 10) + j)) * HD;
        ((float4*)(ws + lr*HD))[tid] = ((const float4*)src)[tid];
    }
    if (tid < UNITS) c_s[tid] = 0.f;
    __syncthreads();

    const int warp = tid >> 5, lane = tid & 31;

    for (int t = 0; t < TT; t++) {
        // prefetch per-unit xg (DRAM latency hidden behind the dot phase)
        float xgv0=0.f, xgv1=0.f, xgv2=0.f, xgv3=0.f;
        if (tid < UNITS && (u0 + tid) < 2*HD) {
            int u = u0 + tid, dir = u >> 10, j = u & (HD-1);
            int tt = dir ? (TT-1-t) : t;
            const float* p = (dir ? xgb : xgf) + (size_t)tt * G4H + j;
            xgv0 = __ldg(p); xgv1 = __ldg(p+HD); xgv2 = __ldg(p+2*HD); xgv3 = __ldg(p+3*HD);
        }
        // gate-row dot products: warp w handles rows [w*7, w*7+7)
        float hreg[32];
        int curdir = -1;
        #pragma unroll
        for (int r = 0; r < 7; r++) {
            int lr = warp*7 + r;
            int u = u0 + (lr >> 2);
            if (u >= 2*HD) break;
            int dir = u >> 10;
            if (dir != curdir) {
                curdir = dir;
                const float* hb = &g_hbuf[dir][t & 1][0];
                #pragma unroll
                for (int i = 0; i < 32; i++) hreg[i] = __ldcg(hb + lane + (i << 5));
            }
            const float* w = ws + lr*HD + lane;
            float acc = 0.f;
            #pragma unroll
            for (int i = 0; i < 32; i++) acc = fmaf(w[i << 5], hreg[i], acc);
            #pragma unroll
            for (int off = 16; off; off >>= 1) acc += __shfl_down_sync(0xFFFFFFFFu, acc, off);
            if (lane == 0) dot_s[lr] = acc;
        }
        __syncthreads();
        // combine gates -> (c, h)
        if (tid < UNITS && (u0 + tid) < 2*HD) {
            int u = u0 + tid, dir = u >> 10, j = u & (HD-1);
            int lrb = tid << 2;
            float gi = xgv0 + dot_s[lrb+0];
            float gf = xgv1 + dot_s[lrb+1];
            float gg = xgv2 + dot_s[lrb+2];
            float go = xgv3 + dot_s[lrb+3];
            float si = 1.f / (1.f + expf(-gi));
            float sf = 1.f / (1.f + expf(-gf));
            float so = 1.f / (1.f + expf(-go));
            float c = sf * c_s[tid] + si * tanhf(gg);
            c_s[tid] = c;
            float h = so * tanhf(c);
            __stcg(&g_hbuf[dir][(t+1) & 1][j], h);
            int tt = dir ? (TT-1-t) : t;
            hout[(size_t)tt * 2048 + (dir << 10) + j] = h;
        }
        __threadfence();
        __syncthreads();
        if (tid == 0) {
            atomicAdd(&g_bar, 1u);
            unsigned tgt = (unsigned)(t+1) * gridDim.x;
            while (atomicAdd(&g_bar, 0u) < tgt) __nanosleep(64);
        }
        __syncthreads();
    }
}

// ---------------- feats = h1 @ w_out^T + b_out ----------------
__global__ void feats_kernel(const float* __restrict__ h1, const float* __restrict__ wout,
                             const float* __restrict__ bout, float* __restrict__ feats)
{
    __shared__ float red[5][256];
    int t = blockIdx.x, tid = threadIdx.x;
    const float* hrow = h1 + (size_t)t * 2048;
    float p0=0,p1=0,p2=0,p3=0,p4=0;
    for (int k = tid; k < 2048; k += 256) {
        float hv = hrow[k];
        p0 = fmaf(hv, __ldg(wout + 0*2048 + k), p0);
        p1 = fmaf(hv, __ldg(wout + 1*2048 + k), p1);
        p2 = fmaf(hv, __ldg(wout + 2*2048 + k), p2);
        p3 = fmaf(hv, __ldg(wout + 3*2048 + k), p3);
        p4 = fmaf(hv, __ldg(wout + 4*2048 + k), p4);
    }
    red[0][tid]=p0; red[1][tid]=p1; red[2][tid]=p2; red[3][tid]=p3; red[4][tid]=p4;
    __syncthreads();
    if (tid < 5) {
        float s = 0.f;
        for (int i = 0; i < 256; i++) s += red[tid][i];
        feats[t*5 + tid] = s + bout[tid];
    }
}

// ---------------- Viterbi DP + backtrace (single block, one warp) ----------------
#define NEGV (-10000.0f)
__global__ void viterbi_kernel(const float* __restrict__ feats, const float* __restrict__ trans,
                               float* __restrict__ out, int out_size)
{
    __shared__ unsigned char bp[TT*5];   // 40960 B
    __shared__ float fch[256*5];         //  5120 B
    const int lane = threadIdx.x;
    float trow[5] = {0,0,0,0,0};
    if (lane < 5) {
        #pragma unroll
        for (int p = 0; p < 5; p++) trow[p] = trans[lane*5 + p];
    }
    float fv[5];
    #pragma unroll
    for (int p = 0; p < 5; p++) fv[p] = (p == 3) ? 0.f : NEGV;  // START_INDEX=3

    for (int ch = 0; ch < TT/256; ch++) {
        const float* src = feats + ch*256*5;
        for (int i = lane; i < 256*5; i += 32) fch[i] = src[i];
        __syncwarp();
        for (int s = 0; s < 256; s++) {
            float best = fv[0] + trow[0]; int arg = 0;
            #pragma unroll
            for (int p = 1; p < 5; p++) { float v = fv[p] + trow[p]; if (v > best) { best = v; arg = p; } }
            float fe = (lane < 5) ? fch[s*5 + lane] : 0.f;
            float nv = best + fe;
            if (lane < 5) bp[(ch*256 + s)*5 + lane] = (unsigned char)arg;
            #pragma unroll
            for (int p = 0; p < 5; p++) fv[p] = __shfl_sync(0xFFFFFFFFu, nv, p);
        }
        __syncwarp();
    }
    // terminal: fv + transitions[STOP_INDEX=4]
    float term = (lane < 5) ? (fv[lane] + trans[4*5 + lane]) : (4.f*NEGV);
    float t0 = __shfl_sync(0xFFFFFFFFu, term, 0);
    float t1 = __shfl_sync(0xFFFFFFFFu, term, 1);
    float t2 = __shfl_sync(0xFFFFFFFFu, term, 2);
    float t3 = __shfl_sync(0xFFFFFFFFu, term, 3);
    float t4 = __shfl_sync(0xFFFFFFFFu, term, 4);
    if (lane == 0) {
        float best = t0; int lbl = 0;
        if (t1 > best) { best = t1; lbl = 1; }
        if (t2 > best) { best = t2; lbl = 2; }
        if (t3 > best) { best = t3; lbl = 3; }
        if (t4 > best) { best = t4; lbl = 4; }
        if (out_size >= TT + 1) {
            int base = out_size - TT;        // expected 1: [score, path...]
            out[0] = best;
            out[base + TT - 1] = (float)lbl;
            for (int t = TT - 2; t >= 0; t--) { lbl = bp[(t+1)*5 + lbl]; out[base + t] = (float)lbl; }
        } else if (out_size >= TT) {         // path only
            int base = out_size - TT;
            out[base + TT - 1] = (float)lbl;
            for (int t = TT - 2; t >= 0; t--) { lbl = bp[(t+1)*5 + lbl]; out[base + t] = (float)lbl; }
        } else if (out_size >= 1) {          // score only
            out[0] = best;
        }
    }
}

// ---------------- host launch ----------------
extern "C" void kernel_launch(void* const* d_in, const int* in_sizes, int n_in,
                              void* d_out, int out_size)
{
    const float* hours    = (const float*)d_in[0];
    const float* w_ih_l0  = (const float*)d_in[1];
    const float* w_hh_l0  = (const float*)d_in[2];
    const float* b_ih_l0  = (const float*)d_in[3];
    const float* b_hh_l0  = (const float*)d_in[4];
    const float* w_ih_l0r = (const float*)d_in[5];
    const float* w_hh_l0r = (const float*)d_in[6];
    const float* b_ih_l0r = (const float*)d_in[7];
    const float* b_hh_l0r = (const float*)d_in[8];
    const float* w_ih_l1  = (const float*)d_in[9];
    const float* w_hh_l1  = (const float*)d_in[10];
    const float* b_ih_l1  = (const float*)d_in[11];
    const float* b_hh_l1  = (const float*)d_in[12];
    const float* w_ih_l1r = (const float*)d_in[13];
    const float* w_hh_l1r = (const float*)d_in[14];
    const float* b_ih_l1r = (const float*)d_in[15];
    const float* b_hh_l1r = (const float*)d_in[16];
    const float* w_out    = (const float*)d_in[17];
    const float* b_out    = (const float*)d_in[18];
    const float* trans    = (const float*)d_in[19];

    float *xg0, *h0, *h1, *feats;
    cudaGetSymbolAddress((void**)&xg0,   g_xg);
    cudaGetSymbolAddress((void**)&h0,    g_h0);
    cudaGetSymbolAddress((void**)&h1,    g_h1);
    cudaGetSymbolAddress((void**)&feats, g_feats);
    float* xg1 = xg0 + (size_t)TT * G4H;

    cudaFuncSetAttribute(lstm_kernel, cudaFuncAttributeMaxDynamicSharedMemorySize, SMEM_WS);

    dim3 gemm_grid(G4H/BN, TT/BM);  // (32, 64)

    // layer 0: input contributions + recurrence
    sgemm_bias<<<gemm_grid, 256>>>(hours, w_ih_l0,  b_ih_l0,  b_hh_l0,  xg0, TT, G4H, 512);
    sgemm_bias<<<gemm_grid, 256>>>(hours, w_ih_l0r, b_ih_l0r, b_hh_l0r, xg1, TT, G4H, 512);
    init_kernel<<<16, 256>>>();
    lstm_kernel<<<NBLK, 256, SMEM_WS>>>(xg0, xg1, w_hh_l0, w_hh_l0r, h0);

    // layer 1
    sgemm_bias<<<gemm_grid, 256>>>(h0, w_ih_l1,  b_ih_l1,  b_hh_l1,  xg0, TT, G4H, 2048);
    sgemm_bias<<<gemm_grid, 256>>>(h0, w_ih_l1r, b_ih_l1r, b_hh_l1r, xg1, TT, G4H, 2048);
    init_kernel<<<16, 256>>>();
    lstm_kernel<<<NBLK, 256, SMEM_WS>>>(xg0, xg1, w_hh_l1, w_hh_l1r, h1);

    // projection + Viterbi
    feats_kernel<<<TT, 256>>>(h1, w_out, b_out, feats);
    viterbi_kernel<<<1, 32>>>(feats, trans, (float*)d_out, out_size);
}

// round 2
// speedup vs baseline: 1.1263x; 1.1263x over previous
#include <cuda_runtime.h>
#include <cuda_bf16.h>
#include <math.h>

#define TT   8192
#define HD   1024
#define G4H  4096
#define UNITS 14              // hidden units per block (1024 units over 74 blocks/dir)
#define NROWS (UNITS*4)       // 56 gate rows per block
#define NBDIR 74
#define NBLK  (2*NBDIR)
#define SMEM_WS (NROWS*HD*4)  // 229376 bytes

// ---------------- static device scratch (no allocs allowed) ----------------
__device__ float    g_xg[2][TT][G4H];        // per-direction input contributions (reused L0/L1)
__device__ float    g_h0[(size_t)TT*2048];   // layer0 output [T,2H]
__device__ float    g_h1[(size_t)TT*2048];   // layer1 output [T,2H]
__device__ float    g_feats[TT*5];
__device__ float    g_hbuf[2][2][HD];        // [dir][ping][H]
__device__ unsigned g_ctr2[2];               // per-direction step counters

// ---------------- barrier primitives ----------------
__device__ __forceinline__ unsigned ld_acq(const unsigned* p) {
    unsigned v;
    asm volatile("ld.acquire.gpu.global.u32 %0, [%1];" : "=r"(v) : "l"(p) : "memory");
    return v;
}
__device__ __forceinline__ void red_rel_add1(unsigned* p) {
    asm volatile("red.release.gpu.global.add.u32 [%0], 1;" :: "l"(p) : "memory");
}

// ---------------- init: zero h state + barriers ----------------
__global__ void init_kernel() {
    int i = blockIdx.x * blockDim.x + threadIdx.x;
    if (i < 2*2*HD) ((float*)g_hbuf)[i] = 0.f;
    if (i < 2) g_ctr2[i] = 0u;
}

// ---------------- fp32 SGEMM (double-buffered): C = A @ W^T + b1 + b2 ----------------
#define BM 128
#define BN 128
#define BK 16
__global__ void __launch_bounds__(256) sgemm_bias(
    const float* __restrict__ A, const float* __restrict__ W,
    const float* __restrict__ b1, const float* __restrict__ b2,
    float* __restrict__ C, int M, int N, int K)
{
    __shared__ float As[2][BK][BM+4];
    __shared__ float Bs[2][BK][BN+4];
    const int tid = threadIdx.x;
    const int bm0 = blockIdx.y * BM;
    const int bn0 = blockIdx.x * BN;
    const int tx = tid & 15, ty = tid >> 4;
    const int lrow = tid >> 2;          // 0..63
    const int lc4  = (tid & 3) * 4;     // 0,4,8,12

    float acc[8][8];
    #pragma unroll
    for (int i = 0; i < 8; i++)
        #pragma unroll
        for (int j = 0; j < 8; j++) acc[i][j] = 0.f;

    float4 ra[2], rb[2];
    // prologue: load k0=0 tile
    #pragma unroll
    for (int h = 0; h < 2; h++) {
        int row = lrow + h*64;
        ra[h] = *(const float4*)(A + (size_t)(bm0+row)*K + lc4);
        rb[h] = *(const float4*)(W + (size_t)(bn0+row)*K + lc4);
    }
    #pragma unroll
    for (int h = 0; h < 2; h++) {
        int row = lrow + h*64;
        As[0][lc4+0][row] = ra[h].x; As[0][lc4+1][row] = ra[h].y;
        As[0][lc4+2][row] = ra[h].z; As[0][lc4+3][row] = ra[h].w;
        Bs[0][lc4+0][row] = rb[h].x; Bs[0][lc4+1][row] = rb[h].y;
        Bs[0][lc4+2][row] = rb[h].z; Bs[0][lc4+3][row] = rb[h].w;
    }
    __syncthreads();

    int buf = 0;
    for (int k0 = BK; k0 <= K; k0 += BK) {
        if (k0 < K) {
            #pragma unroll
            for (int h = 0; h < 2; h++) {
                int row = lrow + h*64;
                ra[h] = *(const float4*)(A + (size_t)(bm0+row)*K + k0 + lc4);
                rb[h] = *(const float4*)(W + (size_t)(bn0+row)*K + k0 + lc4);
            }
        }
        #pragma unroll
        for (int kk = 0; kk < BK; kk++) {
            float a[8], b[8];
            #pragma unroll
            for (int i = 0; i < 8; i++) a[i] = As[buf][kk][ty*8+i];
            #pragma unroll
            for (int j = 0; j < 8; j++) b[j] = Bs[buf][kk][tx*8+j];
            #pragma unroll
            for (int i = 0; i < 8; i++)
                #pragma unroll
                for (int j = 0; j < 8; j++) acc[i][j] = fmaf(a[i], b[j], acc[i][j]);
        }
        if (k0 < K) {
            __syncthreads();
            int nb = buf ^ 1;
            #pragma unroll
            for (int h = 0; h < 2; h++) {
                int row = lrow + h*64;
                As[nb][lc4+0][row] = ra[h].x; As[nb][lc4+1][row] = ra[h].y;
                As[nb][lc4+2][row] = ra[h].z; As[nb][lc4+3][row] = ra[h].w;
                Bs[nb][lc4+0][row] = rb[h].x; Bs[nb][lc4+1][row] = rb[h].y;
                Bs[nb][lc4+2][row] = rb[h].z; Bs[nb][lc4+3][row] = rb[h].w;
            }
            __syncthreads();
            buf = nb;
        }
    }
    float bv[8];
    #pragma unroll
    for (int j = 0; j < 8; j++) { int n = bn0 + tx*8 + j; bv[j] = b1[n] + b2[n]; }
    #pragma unroll
    for (int i = 0; i < 8; i++) {
        size_t mrow = (size_t)(bm0 + ty*8 + i) * N;
        #pragma unroll
        for (int j = 0; j < 8; j++) C[mrow + bn0 + tx*8 + j] = acc[i][j] + bv[j];
    }
}

// ---------------- persistent bidirectional LSTM layer ----------------
// 148 blocks: blocks [0,74) = forward dir, [74,148) = backward dir.
// Each block owns UNITS=14 hidden units; W_hh slice (56 rows x 1024 fp32 = 229KB)
// resident in dynamic smem for all 8192 steps. Per-direction flag barrier:
// one red.release arrival per block, ld.acquire polling (no atomic-ALU serialization).
__global__ void __launch_bounds__(256, 1) lstm_kernel(
    const float* __restrict__ xgf, const float* __restrict__ xgb,
    const float* __restrict__ whf, const float* __restrict__ whb,
    float* __restrict__ hout)
{
    extern __shared__ float ws[];
    __shared__ float dot_s[NROWS];
    __shared__ float c_s[UNITS];
    const int tid  = threadIdx.x;
    const int dir  = (blockIdx.x >= NBDIR) ? 1 : 0;
    const int bb   = blockIdx.x - dir * NBDIR;
    const int u0   = bb * UNITS;                    // unit offset within this direction
    const float* wh = dir ? whb : whf;
    const float* xg = dir ? xgb : xgf;
    unsigned* ctr = &g_ctr2[dir];

    // stage weight slice into smem (coalesced float4)
    for (int lr = 0; lr < NROWS; lr++) {
        int u = u0 + (lr >> 2);
        if (u >= HD) break;
        int gate = lr & 3;
        const float* src = wh + ((size_t)((gate << 10) + u)) * HD;
        ((float4*)(ws + lr*HD))[tid] = ((const float4*)src)[tid];
    }
    if (tid < UNITS) c_s[tid] = 0.f;
    __syncthreads();

    const int warp = tid >> 5, lane = tid & 31;
    const int row0 = warp * 7;
    const int nrow_valid = (u0 + (row0 >> 2) < HD) ?
        min(7, (HD - u0) * 4 - row0) : 0;           // valid rows for this warp
    const int has_unit = (tid < UNITS) && (u0 + tid < HD);

    for (int t = 0; t < TT; t++) {
        const int tt = dir ? (TT-1-t) : t;
        // prefetch per-unit xg early (independent of h)
        float xgv0=0.f, xgv1=0.f, xgv2=0.f, xgv3=0.f;
        if (has_unit) {
            const float* p = xg + (size_t)tt * G4H + (u0 + tid);
            xgv0 = __ldg(p); xgv1 = __ldg(p+HD); xgv2 = __ldg(p+2*HD); xgv3 = __ldg(p+3*HD);
        }
        // wait for all blocks of this direction to have finished step t-1
        if (lane == 0) {
            unsigned tgt = (unsigned)t * NBDIR;
            while (ld_acq(ctr) < tgt) { }
        }
        __syncwarp();

        if (nrow_valid > 0) {
            // load h (prev step) as float4s into registers, once per warp
            const float4* hb = (const float4*)&g_hbuf[dir][t & 1][0];
            float4 hv[8];
            #pragma unroll
            for (int i = 0; i < 8; i++) hv[i] = __ldcg(hb + lane + (i << 5));
            // gate-row dot products
            #pragma unroll
            for (int r = 0; r < 7; r++) {
                if (r >= nrow_valid) break;
                int lr = row0 + r;
                const float4* w4 = (const float4*)(ws + lr*HD);
                float a0 = 0.f, a1 = 0.f;
                #pragma unroll
                for (int i = 0; i < 8; i += 2) {
                    float4 w = w4[lane + (i << 5)];
                    a0 = fmaf(w.x, hv[i].x, a0); a0 = fmaf(w.y, hv[i].y, a0);
                    a0 = fmaf(w.z, hv[i].z, a0); a0 = fmaf(w.w, hv[i].w, a0);
                    float4 v = w4[lane + ((i+1) << 5)];
                    a1 = fmaf(v.x, hv[i+1].x, a1); a1 = fmaf(v.y, hv[i+1].y, a1);
                    a1 = fmaf(v.z, hv[i+1].z, a1); a1 = fmaf(v.w, hv[i+1].w, a1);
                }
                float acc = a0 + a1;
                #pragma unroll
                for (int off = 16; off; off >>= 1) acc += __shfl_down_sync(0xFFFFFFFFu, acc, off);
                if (lane == 0) dot_s[lr] = acc;
            }
        }
        __syncthreads();
        // combine gates -> (c, h); warp 0 only (tid < UNITS)
        if (has_unit) {
            int lrb = tid << 2;
            float gi = xgv0 + dot_s[lrb+0];
            float gf = xgv1 + dot_s[lrb+1];
            float gg = xgv2 + dot_s[lrb+2];
            float go = xgv3 + dot_s[lrb+3];
            float si = 1.f / (1.f + expf(-gi));
            float sf = 1.f / (1.f + expf(-gf));
            float so = 1.f / (1.f + expf(-go));
            float c = sf * c_s[tid] + si * tanhf(gg);
            c_s[tid] = c;
            float h = so * tanhf(c);
            __stcg(&g_hbuf[dir][(t+1) & 1][u0 + tid], h);
            hout[(size_t)tt * 2048 + (dir << 10) + u0 + tid] = h;
        }
        __syncwarp();
        if (tid == 0) red_rel_add1(ctr);   // release: h stores of warp 0 ordered before arrival
        // NOTE: no trailing __syncthreads — other warps run ahead to the poll,
        // which cannot pass until every block (incl. this one) has arrived.
    }
}

// ---------------- feats = h1 @ w_out^T + b_out ----------------
__global__ void feats_kernel(const float* __restrict__ h1, const float* __restrict__ wout,
                             const float* __restrict__ bout, float* __restrict__ feats)
{
    __shared__ float red[5][256];
    int t = blockIdx.x, tid = threadIdx.x;
    const float* hrow = h1 + (size_t)t * 2048;
    float p0=0,p1=0,p2=0,p3=0,p4=0;
    for (int k = tid; k < 2048; k += 256) {
        float hv = hrow[k];
        p0 = fmaf(hv, __ldg(wout + 0*2048 + k), p0);
        p1 = fmaf(hv, __ldg(wout + 1*2048 + k), p1);
        p2 = fmaf(hv, __ldg(wout + 2*2048 + k), p2);
        p3 = fmaf(hv, __ldg(wout + 3*2048 + k), p3);
        p4 = fmaf(hv, __ldg(wout + 4*2048 + k), p4);
    }
    red[0][tid]=p0; red[1][tid]=p1; red[2][tid]=p2; red[3][tid]=p3; red[4][tid]=p4;
    __syncthreads();
    if (tid < 5) {
        float s = 0.f;
        for (int i = 0; i < 256; i++) s += red[tid][i];
        feats[t*5 + tid] = s + bout[tid];
    }
}

// ---------------- Viterbi DP + backtrace (single block, one warp) ----------------
#define NEGV (-10000.0f)
__global__ void viterbi_kernel(const float* __restrict__ feats, const float* __restrict__ trans,
                               float* __restrict__ out, int out_size)
{
    __shared__ unsigned char bp[TT*5];   // 40960 B
    __shared__ float fch[256*5];         //  5120 B
    const int lane = threadIdx.x;
    float trow[5] = {0,0,0,0,0};
    if (lane < 5) {
        #pragma unroll
        for (int p = 0; p < 5; p++) trow[p] = trans[lane*5 + p];
    }
    float fv[5];
    #pragma unroll
    for (int p = 0; p < 5; p++) fv[p] = (p == 3) ? 0.f : NEGV;  // START_INDEX=3

    for (int ch = 0; ch < TT/256; ch++) {
        const float* src = feats + ch*256*5;
        for (int i = lane; i < 256*5; i += 32) fch[i] = src[i];
        __syncwarp();
        for (int s = 0; s < 256; s++) {
            float best = fv[0] + trow[0]; int arg = 0;
            #pragma unroll
            for (int p = 1; p < 5; p++) { float v = fv[p] + trow[p]; if (v > best) { best = v; arg = p; } }
            float fe = (lane < 5) ? fch[s*5 + lane] : 0.f;
            float nv = best + fe;
            if (lane < 5) bp[(ch*256 + s)*5 + lane] = (unsigned char)arg;
            #pragma unroll
            for (int p = 0; p < 5; p++) fv[p] = __shfl_sync(0xFFFFFFFFu, nv, p);
        }
        __syncwarp();
    }
    float term = (lane < 5) ? (fv[lane] + trans[4*5 + lane]) : (4.f*NEGV);
    float t0 = __shfl_sync(0xFFFFFFFFu, term, 0);
    float t1 = __shfl_sync(0xFFFFFFFFu, term, 1);
    float t2 = __shfl_sync(0xFFFFFFFFu, term, 2);
    float t3 = __shfl_sync(0xFFFFFFFFu, term, 3);
    float t4 = __shfl_sync(0xFFFFFFFFu, term, 4);
    if (lane == 0) {
        float best = t0; int lbl = 0;
        if (t1 > best) { best = t1; lbl = 1; }
        if (t2 > best) { best = t2; lbl = 2; }
        if (t3 > best) { best = t3; lbl = 3; }
        if (t4 > best) { best = t4; lbl = 4; }
        if (out_size >= TT + 1) {
            int base = out_size - TT;        // [score, path...]
            out[0] = best;
            out[base + TT - 1] = (float)lbl;
            for (int t = TT - 2; t >= 0; t--) { lbl = bp[(t+1)*5 + lbl]; out[base + t] = (float)lbl; }
        } else if (out_size >= TT) {
            int base = out_size - TT;
            out[base + TT - 1] = (float)lbl;
            for (int t = TT - 2; t >= 0; t--) { lbl = bp[(t+1)*5 + lbl]; out[base + t] = (float)lbl; }
        } else if (out_size >= 1) {
            out[0] = best;
        }
    }
}

// ---------------- host launch ----------------
extern "C" void kernel_launch(void* const* d_in, const int* in_sizes, int n_in,
                              void* d_out, int out_size)
{
    const float* hours    = (const float*)d_in[0];
    const float* w_ih_l0  = (const float*)d_in[1];
    const float* w_hh_l0  = (const float*)d_in[2];
    const float* b_ih_l0  = (const float*)d_in[3];
    const float* b_hh_l0  = (const float*)d_in[4];
    const float* w_ih_l0r = (const float*)d_in[5];
    const float* w_hh_l0r = (const float*)d_in[6];
    const float* b_ih_l0r = (const float*)d_in[7];
    const float* b_hh_l0r = (const float*)d_in[8];
    const float* w_ih_l1  = (const float*)d_in[9];
    const float* w_hh_l1  = (const float*)d_in[10];
    const float* b_ih_l1  = (const float*)d_in[11];
    const float* b_hh_l1  = (const float*)d_in[12];
    const float* w_ih_l1r = (const float*)d_in[13];
    const float* w_hh_l1r = (const float*)d_in[14];
    const float* b_ih_l1r = (const float*)d_in[15];
    const float* b_hh_l1r = (const float*)d_in[16];
    const float* w_out    = (const float*)d_in[17];
    const float* b_out    = (const float*)d_in[18];
    const float* trans    = (const float*)d_in[19];

    float *xg0, *h0, *h1, *feats;
    cudaGetSymbolAddress((void**)&xg0,   g_xg);
    cudaGetSymbolAddress((void**)&h0,    g_h0);
    cudaGetSymbolAddress((void**)&h1,    g_h1);
    cudaGetSymbolAddress((void**)&feats, g_feats);
    float* xg1 = xg0 + (size_t)TT * G4H;

    cudaFuncSetAttribute(lstm_kernel, cudaFuncAttributeMaxDynamicSharedMemorySize, SMEM_WS);

    dim3 gemm_grid(G4H/BN, TT/BM);  // (32, 64)

    // layer 0
    sgemm_bias<<<gemm_grid, 256>>>(hours, w_ih_l0,  b_ih_l0,  b_hh_l0,  xg0, TT, G4H, 512);
    sgemm_bias<<<gemm_grid, 256>>>(hours, w_ih_l0r, b_ih_l0r, b_hh_l0r, xg1, TT, G4H, 512);
    init_kernel<<<16, 256>>>();
    lstm_kernel<<<NBLK, 256, SMEM_WS>>>(xg0, xg1, w_hh_l0, w_hh_l0r, h0);

    // layer 1
    sgemm_bias<<<gemm_grid, 256>>>(h0, w_ih_l1,  b_ih_l1,  b_hh_l1,  xg0, TT, G4H, 2048);
    sgemm_bias<<<gemm_grid, 256>>>(h0, w_ih_l1r, b_ih_l1r, b_hh_l1r, xg1, TT, G4H, 2048);
    init_kernel<<<16, 256>>>();
    lstm_kernel<<<NBLK, 256, SMEM_WS>>>(xg0, xg1, w_hh_l1, w_hh_l1r, h1);

    // projection + Viterbi
    feats_kernel<<<TT, 256>>>(h1, w_out, b_out, feats);
    viterbi_kernel<<<1, 32>>>(feats, trans, (float*)d_out, out_size);
}

// round 3
// speedup vs baseline: 1.4112x; 1.2529x over previous
#include <cuda_runtime.h>
#include <cuda_bf16.h>
#include <math.h>

#define TT    8192
#define HD    1024
#define G4H   4096
#define UPD   7                 // units per block per direction
#define NRD   (UPD*4)           // 28 gate rows per dir per block
#define NBLK  148
// dynamic smem: weights[2][28][512] + hstage[2][1024] + dots[2][28]
#define WS_W      (2*NRD*512)
#define WS_H      (WS_W + 0)
#define OFF_H     (2*NRD*512)
#define OFF_D     (OFF_H + 2*1024)
#define SMEM_LSTM ((OFF_D + 2*NRD + 16) * 4)

// ---------------- static device scratch ----------------
__device__ float    g_xg[2][TT][G4H];
__device__ float    g_h0[(size_t)TT*2048];
__device__ float    g_h1[(size_t)TT*2048];
__device__ float    g_feats[TT*5];
__device__ float    g_hbuf[2][2][HD];        // [dir][ping][H]
__device__ unsigned g_ctr2[2];

union F2 { float2 f; unsigned long long u; };

// ---------------- barrier primitives ----------------
__device__ __forceinline__ unsigned ld_acq(const unsigned* p) {
    unsigned v;
    asm volatile("ld.acquire.gpu.global.u32 %0, [%1];" : "=r"(v) : "l"(p) : "memory");
    return v;
}
__device__ __forceinline__ void red_rel_add1(unsigned* p) {
    asm volatile("red.release.gpu.global.add.u32 [%0], 1;" :: "l"(p) : "memory");
}
__device__ __forceinline__ void bar_named(int id) {
    asm volatile("bar.sync %0, 128;" :: "r"(id) : "memory");
}

__global__ void init_kernel() {
    int i = blockIdx.x * blockDim.x + threadIdx.x;
    if (i < 2*2*HD) ((float*)g_hbuf)[i] = 0.f;
    if (i < 2) g_ctr2[i] = 0u;
}

// ---------------- fp32 SGEMM, double-buffered, f32x2 FMA ----------------
#define BM 128
#define BN 128
#define BK 16
__global__ void __launch_bounds__(256) sgemm_bias(
    const float* __restrict__ A, const float* __restrict__ W,
    const float* __restrict__ b1, const float* __restrict__ b2,
    float* __restrict__ C, int M, int N, int K)
{
    __shared__ float As[2][BK][BM+4];
    __shared__ float Bs[2][BK][BN+4];
    const int tid = threadIdx.x;
    const int bm0 = blockIdx.y * BM;
    const int bn0 = blockIdx.x * BN;
    const int tx = tid & 15, ty = tid >> 4;
    const int lrow = tid >> 2;
    const int lc4  = (tid & 3) * 4;

    F2 acc[8][4];
    #pragma unroll
    for (int i = 0; i < 8; i++)
        #pragma unroll
        for (int j = 0; j < 4; j++) acc[i][j].u = 0ull;

    float4 ra[2], rb[2];
    #pragma unroll
    for (int h = 0; h < 2; h++) {
        int row = lrow + h*64;
        ra[h] = *(const float4*)(A + (size_t)(bm0+row)*K + lc4);
        rb[h] = *(const float4*)(W + (size_t)(bn0+row)*K + lc4);
    }
    #pragma unroll
    for (int h = 0; h < 2; h++) {
        int row = lrow + h*64;
        As[0][lc4+0][row] = ra[h].x; As[0][lc4+1][row] = ra[h].y;
        As[0][lc4+2][row] = ra[h].z; As[0][lc4+3][row] = ra[h].w;
        Bs[0][lc4+0][row] = rb[h].x; Bs[0][lc4+1][row] = rb[h].y;
        Bs[0][lc4+2][row] = rb[h].z; Bs[0][lc4+3][row] = rb[h].w;
    }
    __syncthreads();

    int buf = 0;
    for (int k0 = BK; k0 <= K; k0 += BK) {
        if (k0 < K) {
            #pragma unroll
            for (int h = 0; h < 2; h++) {
                int row = lrow + h*64;
                ra[h] = *(const float4*)(A + (size_t)(bm0+row)*K + k0 + lc4);
                rb[h] = *(const float4*)(W + (size_t)(bn0+row)*K + k0 + lc4);
            }
        }
        #pragma unroll
        for (int kk = 0; kk < BK; kk++) {
            float a[8]; F2 bp[4];
            #pragma unroll
            for (int i = 0; i < 8; i++) a[i] = As[buf][kk][ty*8+i];
            #pragma unroll
            for (int j = 0; j < 4; j++) bp[j].f = *(const float2*)&Bs[buf][kk][tx*8 + 2*j];
            #pragma unroll
            for (int i = 0; i < 8; i++) {
                F2 ap; ap.f.x = a[i]; ap.f.y = a[i];
                #pragma unroll
                for (int j = 0; j < 4; j++)
                    asm("fma.rn.f32x2 %0, %1, %2, %0;" : "+l"(acc[i][j].u) : "l"(ap.u), "l"(bp[j].u));
            }
        }
        if (k0 < K) {
            __syncthreads();
            int nb = buf ^ 1;
            #pragma unroll
            for (int h = 0; h < 2; h++) {
                int row = lrow + h*64;
                As[nb][lc4+0][row] = ra[h].x; As[nb][lc4+1][row] = ra[h].y;
                As[nb][lc4+2][row] = ra[h].z; As[nb][lc4+3][row] = ra[h].w;
                Bs[nb][lc4+0][row] = rb[h].x; Bs[nb][lc4+1][row] = rb[h].y;
                Bs[nb][lc4+2][row] = rb[h].z; Bs[nb][lc4+3][row] = rb[h].w;
            }
            __syncthreads();
            buf = nb;
        }
    }
    float bv[8];
    #pragma unroll
    for (int j = 0; j < 8; j++) { int n = bn0 + tx*8 + j; bv[j] = b1[n] + b2[n]; }
    #pragma unroll
    for (int i = 0; i < 8; i++) {
        size_t mrow = (size_t)(bm0 + ty*8 + i) * N;
        #pragma unroll
        for (int j = 0; j < 4; j++) {
            C[mrow + bn0 + tx*8 + 2*j + 0] = acc[i][j].f.x + bv[2*j+0];
            C[mrow + bn0 + tx*8 + 2*j + 1] = acc[i][j].f.y + bv[2*j+1];
        }
    }
}

// ---------------- persistent bidirectional LSTM layer ----------------
// 148 blocks x 256 thr. Block owns units [b*7, b*7+7) of BOTH directions.
// Warps 0-3 = forward engine, warps 4-7 = backward engine (decoupled; named
// barriers 1/2). Per warp, 7 gate rows: k[0,512) weights in REGISTERS
// (112 regs), k[512,1024) in smem. h broadcast: staged smem once per group.
__global__ void __launch_bounds__(256, 1) lstm_kernel(
    const float* __restrict__ xgf, const float* __restrict__ xgb,
    const float* __restrict__ whf, const float* __restrict__ whb,
    float* __restrict__ hout)
{
    extern __shared__ float ws[];
    const int tid  = threadIdx.x;
    const int dir  = tid >> 7;           // 0 = fwd, 1 = bwd
    const int gtid = tid & 127;
    const int wg   = gtid >> 5;          // warp in group 0..3
    const int lane = tid & 31;
    const int u0   = blockIdx.x * UPD;   // unit base (same units both dirs)

    const float* wh = dir ? whb : whf;
    const float* xg = dir ? xgb : xgf;
    unsigned* ctr = &g_ctr2[dir];

    float* ws_my  = ws + dir * (NRD*512);          // smem weight half [28][512]
    float4* hs4   = (float4*)(ws + OFF_H + dir*1024);
    float* ds     = ws + OFF_D + dir*NRD;

    // ---- stage weights: regs (k<512) + smem (k>=512) ----
    float4 wreg[UPD][4];
    bool rv[UPD];
    #pragma unroll
    for (int r = 0; r < UPD; r++) {
        int lr = wg*UPD + r;
        int unit = u0 + (lr >> 2);
        rv[r] = (unit < HD);
        if (rv[r]) {
            const float4* src = (const float4*)(wh + ((size_t)(((lr & 3) << 10) + unit)) * HD);
            #pragma unroll
            for (int i = 0; i < 4; i++) wreg[r][i] = __ldg(src + lane + i*32);
        } else {
            #pragma unroll
            for (int i = 0; i < 4; i++) wreg[r][i] = make_float4(0.f,0.f,0.f,0.f);
        }
    }
    for (int idx = gtid; idx < NRD*128; idx += 128) {
        int lr = idx >> 7, q = idx & 127;
        int unit = u0 + (lr >> 2);
        float4 v = make_float4(0.f,0.f,0.f,0.f);
        if (unit < HD) {
            const float4* src = (const float4*)(wh + ((size_t)(((lr & 3) << 10) + unit)) * HD);
            v = __ldg(src + 128 + q);
        }
        ((float4*)(ws_my + lr*512))[q] = v;
    }
    __syncthreads();

    const bool cu = (gtid < UPD) && (u0 + gtid < HD);   // combine-lane valid
    float creg = 0.f;                                    // cell state in register
    const int bid = 1 + dir;

    #pragma unroll 1
    for (int t = 0; t < TT; t++) {
        const int tt = dir ? (TT-1-t) : t;
        // xg prefetch (independent of h; hides DRAM latency under poll)
        float xgv0=0.f, xgv1=0.f, xgv2=0.f, xgv3=0.f;
        if (cu) {
            const float* p = xg + (size_t)tt * G4H + (u0 + gtid);
            xgv0 = __ldg(p); xgv1 = __ldg(p+HD); xgv2 = __ldg(p+2*HD); xgv3 = __ldg(p+3*HD);
        }
        // wait for all blocks' h[t-1] of this direction
        if (gtid == 0) {
            unsigned tgt = (unsigned)t * NBLK;
            while (ld_acq(ctr) < tgt) { }
        }
        bar_named(bid);
        // stage h through smem (one L2 read per group, not per warp)
        {
            const float4* hb4 = (const float4*)&g_hbuf[dir][t & 1][0];
            float4 a = __ldcg(hb4 + gtid);
            float4 b = __ldcg(hb4 + 128 + gtid);
            hs4[gtid] = a; hs4[128 + gtid] = b;
        }
        bar_named(bid);
        // h into registers
        float4 hv[8];
        #pragma unroll
        for (int i = 0; i < 8; i++) hv[i] = hs4[lane + (i << 5)];
        // gate-row dots: half from registers, half from smem
        #pragma unroll
        for (int r = 0; r < UPD; r++) {
            if (!rv[r]) break;
            int lr = wg*UPD + r;
            const float4* w4s = (const float4*)(ws_my + lr*512);
            float a0 = 0.f, a1 = 0.f;
            #pragma unroll
            for (int i = 0; i < 4; i++) {
                float4 w = wreg[r][i];
                a0 = fmaf(w.x, hv[i].x, a0); a0 = fmaf(w.y, hv[i].y, a0);
                a0 = fmaf(w.z, hv[i].z, a0); a0 = fmaf(w.w, hv[i].w, a0);
                float4 v = w4s[lane + (i << 5)];
                a1 = fmaf(v.x, hv[i+4].x, a1); a1 = fmaf(v.y, hv[i+4].y, a1);
                a1 = fmaf(v.z, hv[i+4].z, a1); a1 = fmaf(v.w, hv[i+4].w, a1);
            }
            float acc = a0 + a1;
            #pragma unroll
            for (int off = 16; off; off >>= 1) acc += __shfl_down_sync(0xFFFFFFFFu, acc, off);
            if (lane == 0) ds[lr] = acc;
        }
        bar_named(bid);
        // combine -> (c, h); lanes 0-6 of group warp 0
        if (cu) {
            int lrb = gtid << 2;
            float gi = xgv0 + ds[lrb+0];
            float gf = xgv1 + ds[lrb+1];
            float gg = xgv2 + ds[lrb+2];
            float go = xgv3 + ds[lrb+3];
            float si = 1.f / (1.f + expf(-gi));
            float sf = 1.f / (1.f + expf(-gf));
            float so = 1.f / (1.f + expf(-go));
            creg = sf * creg + si * tanhf(gg);
            float h = so * tanhf(creg);
            __stcg(&g_hbuf[dir][(t+1) & 1][u0 + gtid], h);
            hout[(size_t)tt * 2048 + (dir << 10) + u0 + gtid] = h;
        }
        __syncwarp();
        if (gtid == 0) red_rel_add1(ctr);
        // warps 1-3 run ahead to next poll barrier; cannot pass until all arrive
    }
}

// ---------------- feats = h1 @ w_out^T + b_out ----------------
__global__ void feats_kernel(const float* __restrict__ h1, const float* __restrict__ wout,
                             const float* __restrict__ bout, float* __restrict__ feats)
{
    __shared__ float red[5][256];
    int t = blockIdx.x, tid = threadIdx.x;
    const float* hrow = h1 + (size_t)t * 2048;
    float p0=0,p1=0,p2=0,p3=0,p4=0;
    for (int k = tid; k < 2048; k += 256) {
        float hv = hrow[k];
        p0 = fmaf(hv, __ldg(wout + 0*2048 + k), p0);
        p1 = fmaf(hv, __ldg(wout + 1*2048 + k), p1);
        p2 = fmaf(hv, __ldg(wout + 2*2048 + k), p2);
        p3 = fmaf(hv, __ldg(wout + 3*2048 + k), p3);
        p4 = fmaf(hv, __ldg(wout + 4*2048 + k), p4);
    }
    red[0][tid]=p0; red[1][tid]=p1; red[2][tid]=p2; red[3][tid]=p3; red[4][tid]=p4;
    __syncthreads();
    if (tid < 5) {
        float s = 0.f;
        for (int i = 0; i < 256; i++) s += red[tid][i];
        feats[t*5 + tid] = s + bout[tid];
    }
}

// ---------------- Viterbi DP + backtrace ----------------
#define NEGV (-10000.0f)
__global__ void viterbi_kernel(const float* __restrict__ feats, const float* __restrict__ trans,
                               float* __restrict__ out, int out_size)
{
    __shared__ unsigned char bp[TT*5];
    __shared__ float fch[256*5];
    const int lane = threadIdx.x;
    float trow[5] = {0,0,0,0,0};
    if (lane < 5) {
        #pragma unroll
        for (int p = 0; p < 5; p++) trow[p] = trans[lane*5 + p];
    }
    float fv[5];
    #pragma unroll
    for (int p = 0; p < 5; p++) fv[p] = (p == 3) ? 0.f : NEGV;

    for (int ch = 0; ch < TT/256; ch++) {
        const float* src = feats + ch*256*5;
        for (int i = lane; i < 256*5; i += 32) fch[i] = src[i];
        __syncwarp();
        for (int s = 0; s < 256; s++) {
            float best = fv[0] + trow[0]; int arg = 0;
            #pragma unroll
            for (int p = 1; p < 5; p++) { float v = fv[p] + trow[p]; if (v > best) { best = v; arg = p; } }
            float fe = (lane < 5) ? fch[s*5 + lane] : 0.f;
            float nv = best + fe;
            if (lane < 5) bp[(ch*256 + s)*5 + lane] = (unsigned char)arg;
            #pragma unroll
            for (int p = 0; p < 5; p++) fv[p] = __shfl_sync(0xFFFFFFFFu, nv, p);
        }
        __syncwarp();
    }
    float term = (lane < 5) ? (fv[lane] + trans[4*5 + lane]) : (4.f*NEGV);
    float t0 = __shfl_sync(0xFFFFFFFFu, term, 0);
    float t1 = __shfl_sync(0xFFFFFFFFu, term, 1);
    float t2 = __shfl_sync(0xFFFFFFFFu, term, 2);
    float t3 = __shfl_sync(0xFFFFFFFFu, term, 3);
    float t4 = __shfl_sync(0xFFFFFFFFu, term, 4);
    if (lane == 0) {
        float best = t0; int lbl = 0;
        if (t1 > best) { best = t1; lbl = 1; }
        if (t2 > best) { best = t2; lbl = 2; }
        if (t3 > best) { best = t3; lbl = 3; }
        if (t4 > best) { best = t4; lbl = 4; }
        if (out_size >= TT + 1) {
            int base = out_size - TT;
            out[0] = best;
            out[base + TT - 1] = (float)lbl;
            for (int t = TT - 2; t >= 0; t--) { lbl = bp[(t+1)*5 + lbl]; out[base + t] = (float)lbl; }
        } else if (out_size >= TT) {
            int base = out_size - TT;
            out[base + TT - 1] = (float)lbl;
            for (int t = TT - 2; t >= 0; t--) { lbl = bp[(t+1)*5 + lbl]; out[base + t] = (float)lbl; }
        } else if (out_size >= 1) {
            out[0] = best;
        }
    }
}

// ---------------- host launch ----------------
extern "C" void kernel_launch(void* const* d_in, const int* in_sizes, int n_in,
                              void* d_out, int out_size)
{
    const float* hours    = (const float*)d_in[0];
    const float* w_ih_l0  = (const float*)d_in[1];
    const float* w_hh_l0  = (const float*)d_in[2];
    const float* b_ih_l0  = (const float*)d_in[3];
    const float* b_hh_l0  = (const float*)d_in[4];
    const float* w_ih_l0r = (const float*)d_in[5];
    const float* w_hh_l0r = (const float*)d_in[6];
    const float* b_ih_l0r = (const float*)d_in[7];
    const float* b_hh_l0r = (const float*)d_in[8];
    const float* w_ih_l1  = (const float*)d_in[9];
    const float* w_hh_l1  = (const float*)d_in[10];
    const float* b_ih_l1  = (const float*)d_in[11];
    const float* b_hh_l1  = (const float*)d_in[12];
    const float* w_ih_l1r = (const float*)d_in[13];
    const float* w_hh_l1r = (const float*)d_in[14];
    const float* b_ih_l1r = (const float*)d_in[15];
    const float* b_hh_l1r = (const float*)d_in[16];
    const float* w_out    = (const float*)d_in[17];
    const float* b_out    = (const float*)d_in[18];
    const float* trans    = (const float*)d_in[19];

    float *xg0, *h0, *h1, *feats;
    cudaGetSymbolAddress((void**)&xg0,   g_xg);
    cudaGetSymbolAddress((void**)&h0,    g_h0);
    cudaGetSymbolAddress((void**)&h1,    g_h1);
    cudaGetSymbolAddress((void**)&feats, g_feats);
    float* xg1 = xg0 + (size_t)TT * G4H;

    cudaFuncSetAttribute(lstm_kernel, cudaFuncAttributeMaxDynamicSharedMemorySize, SMEM_LSTM);

    dim3 gemm_grid(G4H/BN, TT/BM);

    sgemm_bias<<<gemm_grid, 256>>>(hours, w_ih_l0,  b_ih_l0,  b_hh_l0,  xg0, TT, G4H, 512);
    sgemm_bias<<<gemm_grid, 256>>>(hours, w_ih_l0r, b_ih_l0r, b_hh_l0r, xg1, TT, G4H, 512);
    init_kernel<<<16, 256>>>();
    lstm_kernel<<<NBLK, 256, SMEM_LSTM>>>(xg0, xg1, w_hh_l0, w_hh_l0r, h0);

    sgemm_bias<<<gemm_grid, 256>>>(h0, w_ih_l1,  b_ih_l1,  b_hh_l1,  xg0, TT, G4H, 2048);
    sgemm_bias<<<gemm_grid, 256>>>(h0, w_ih_l1r, b_ih_l1r, b_hh_l1r, xg1, TT, G4H, 2048);
    init_kernel<<<16, 256>>>();
    lstm_kernel<<<NBLK, 256, SMEM_LSTM>>>(xg0, xg1, w_hh_l1, w_hh_l1r, h1);

    feats_kernel<<<TT, 256>>>(h1, w_out, b_out, feats);
    viterbi_kernel<<<1, 32>>>(feats, trans, (float*)d_out, out_size);
}